// round 11
// baseline (speedup 1.0000x reference)
#include <cuda_runtime.h>
#include <cstdint>

// Conv4d via tf32 mma.sync.m16n8k8 implicit GEMM, round 11.
// R9/R10 tiling (warp = 64m x 32co, CTA = 2 d-layers), fully-unrolled taps,
// even/odd explicit B double-buffer (no register rotation MOVs).

__device__ __forceinline__ float to_tf32(float v) {
    float r; asm("cvt.rna.tf32.f32 %0, %1;" : "=f"(r) : "f"(v)); return r;
}
__device__ __forceinline__ void mma16n8k8(float* d,
    uint32_t a0, uint32_t a1, uint32_t a2, uint32_t a3, uint32_t b0, uint32_t b1) {
    asm volatile("mma.sync.aligned.m16n8k8.row.col.f32.tf32.tf32.f32 "
                 "{%0,%1,%2,%3}, {%4,%5,%6,%7}, {%8,%9}, {%0,%1,%2,%3};"
                 : "+f"(d[0]), "+f"(d[1]), "+f"(d[2]), "+f"(d[3])
                 : "r"(a0), "r"(a1), "r"(a2), "r"(a3), "r"(b0), "r"(b1));
}

// B fragments: [kt][tap][p(2)][lane(32)] float4 = (b0,b1 of nt=2p | b0,b1 of nt=2p+1)
__device__ float4 g_fB[3 * 27 * 2 * 32];

__global__ void prep_fB(const float* __restrict__ weight) {
    int i = blockIdx.x * blockDim.x + threadIdx.x;
    if (i >= 5184) return;
    int lane = i & 31;
    int p    = (i >> 5) & 1;
    int kttap = i >> 6;
    int tap = kttap % 27, kt = kttap / 27;
    int g = lane >> 2, k0 = lane & 3;
    int co0 = (2 * p) * 8 + g, co1 = co0 + 8;
    float4 f;
    f.x = to_tf32(weight[((kt * 32 + co0) * 8 + k0) * 27 + tap]);
    f.y = to_tf32(weight[((kt * 32 + co0) * 8 + k0 + 4) * 27 + tap]);
    f.z = to_tf32(weight[((kt * 32 + co1) * 8 + k0) * 27 + tap]);
    f.w = to_tf32(weight[((kt * 32 + co1) * 8 + k0 + 4) * 27 + tap]);
    g_fB[i] = f;
}

#define NT 128
#define PLANE 968                 // 4*5*48=960 +8 pad: c-plane bank offsets {0,8,16,24}

__global__ void __launch_bounds__(NT, 4) conv4d_mma(
    const float* __restrict__ x, const float* __restrict__ bias,
    float* __restrict__ out)
{
    __shared__ __align__(16) float slab[8 * PLANE];   // [ci8][dd4][hh5][ww48] 31 KB
    __shared__ float sbias[32];

    const int tid  = threadIdx.x;
    const int wid  = tid >> 5, lane = tid & 31;
    const int g    = lane >> 2, c = lane & 3;
    const int dsel = wid >> 1;
    const int mhalf= wid & 1;

    const int hi  = blockIdx.x;                // 0..13
    const int dy0 = blockIdx.y * 2;
    const int bz  = blockIdx.z;
    const int h0  = (hi < 13) ? hi * 3 : 37;   // overlap rows recompute same values
    const int b   = bz >> 4;
    const int t   = bz & 15;

    if (tid < 32) {
        float s = 0.f;
        #pragma unroll
        for (int kt = 0; kt < 3; ++kt) {
            int tf = t + kt - 1;
            if (tf >= 0 && tf < 16) s += bias[kt * 32 + tid];
        }
        sbias[tid] = s;
    }
    for (int i = tid; i < 8 * PLANE; i += NT) slab[i] = 0.f;   // halo stays 0

    // A row base pointers: rows r = mhalf*64 + mt*16 + g + j*8
    const float* aBase[4][2];
    #pragma unroll
    for (int mt = 0; mt < 4; ++mt)
        #pragma unroll
        for (int j = 0; j < 2; ++j) {
            int r  = mhalf * 64 + mt * 16 + g + j * 8;
            int rr = (r < 126) ? r : 125;
            int hl = rr / 42, wi = rr - hl * 42;
            aBase[mt][j] = slab + c * PLANE + dsel * 240 + hl * 48 + wi + 3;
        }

    float acc[4][4][4];
    #pragma unroll
    for (int mt = 0; mt < 4; ++mt)
        #pragma unroll
        for (int nt = 0; nt < 4; ++nt)
            #pragma unroll
            for (int k = 0; k < 4; ++k) acc[mt][nt][k] = 0.f;

    for (int kt = 0; kt < 3; ++kt) {
        const int tf = t + kt - 1;
        if (tf < 0 || tf >= 16) continue;       // uniform across block
        __syncthreads();

        // ---- stage slab: 8ci x 4dd x 5hh rows, 10 float4 per row ----
        const float* xg = x + b * 8192000 + tf * 64000;
        for (int idx = tid; idx < 1600; idx += NT) {
            int ci  = idx / 200;
            int rem = idx - ci * 200;
            int row = rem / 10, q = rem - row * 10;
            int dd  = row / 5,  hh = row - dd * 5;
            int gd = dy0 + dd - 1, gh = h0 + hh - 1;
            if ((unsigned)gd < 40u && (unsigned)gh < 40u) {
                float4 v = *(const float4*)(xg + ci * 1024000 + gd * 1600 + gh * 40 + q * 4);
                v.x = to_tf32(v.x); v.y = to_tf32(v.y);
                v.z = to_tf32(v.z); v.w = to_tf32(v.w);
                *(float4*)(slab + ci * PLANE + dd * 240 + hh * 48 + 4 + q * 4) = v;
            }
        }
        __syncthreads();

        // ---- 27 taps fully unrolled, even/odd B buffers (no rotation MOVs) ----
        const float4* fb = g_fB + (kt * 27) * 64 + lane;
        float4 e0 = __ldg(fb), e1 = __ldg(fb + 32);         // tap 0 (even buf)
        float4 o0, o1;

        #pragma unroll
        for (int tap = 0; tap < 27; ++tap) {
            const int kd = tap / 9, kh = (tap % 9) / 3, kw = tap % 3;
            const int sh = kd * 240 + kh * 48 + kw;          // immediate

            // prefetch tap+1 into the *other* buffer
            if (tap + 1 < 27) {
                if ((tap & 1) == 0) { o0 = __ldg(fb + (tap + 1) * 64); o1 = __ldg(fb + (tap + 1) * 64 + 32); }
                else                { e0 = __ldg(fb + (tap + 1) * 64); e1 = __ldg(fb + (tap + 1) * 64 + 32); }
            }
            const float4 f0 = ((tap & 1) == 0) ? e0 : o0;
            const float4 f1 = ((tap & 1) == 0) ? e1 : o1;
            const uint32_t bb0 = __float_as_uint(f0.x), bb1 = __float_as_uint(f0.y);
            const uint32_t bb2 = __float_as_uint(f0.z), bb3 = __float_as_uint(f0.w);
            const uint32_t bc0 = __float_as_uint(f1.x), bc1 = __float_as_uint(f1.y);
            const uint32_t bc2 = __float_as_uint(f1.z), bc3 = __float_as_uint(f1.w);

            #pragma unroll
            for (int mt = 0; mt < 4; ++mt) {
                uint32_t a0 = __float_as_uint(aBase[mt][0][sh]);
                uint32_t a1 = __float_as_uint(aBase[mt][1][sh]);
                uint32_t a2 = __float_as_uint(aBase[mt][0][sh + 4 * PLANE]);
                uint32_t a3 = __float_as_uint(aBase[mt][1][sh + 4 * PLANE]);
                mma16n8k8(acc[mt][0], a0, a1, a2, a3, bb0, bb1);
                mma16n8k8(acc[mt][1], a0, a1, a2, a3, bb2, bb3);
                mma16n8k8(acc[mt][2], a0, a1, a2, a3, bc0, bc1);
                mma16n8k8(acc[mt][3], a0, a1, a2, a3, bc2, bc3);
            }
        }
    }

    // ---- epilogue: bias + masked stores ----
    const int dyw = dy0 + dsel;
    #pragma unroll
    for (int mt = 0; mt < 4; ++mt) {
        #pragma unroll
        for (int j = 0; j < 2; ++j) {
            int r = mhalf * 64 + mt * 16 + g + j * 8;
            if (r >= 126) continue;
            int hl = r / 42, wi = r - hl * 42;
            if (wi >= 40) continue;
            int sp = dyw * 1600 + (h0 + hl) * 40 + wi;
            #pragma unroll
            for (int nt = 0; nt < 4; ++nt) {
                int co = nt * 8 + 2 * c;
                out[((b * 32 + co) * 16 + t) * 64000 + sp]     = acc[mt][nt][j * 2]     + sbias[co];
                out[((b * 32 + co + 1) * 16 + t) * 64000 + sp] = acc[mt][nt][j * 2 + 1] + sbias[co + 1];
            }
        }
    }
}

extern "C" void kernel_launch(void* const* d_in, const int* in_sizes, int n_in,
                              void* d_out, int out_size) {
    const float* x = nullptr; const float* w = nullptr; const float* bias = nullptr;
    for (int i = 0; i < n_in; ++i) {
        if (in_sizes[i] == 16384000)    x    = (const float*)d_in[i];
        else if (in_sizes[i] == 20736)  w    = (const float*)d_in[i];
        else if (in_sizes[i] == 96)     bias = (const float*)d_in[i];
    }
    float* out = (float*)d_out;
    prep_fB<<<21, 256>>>(w);
    dim3 grid(14, 20, 32);
    conv4d_mma<<<grid, NT>>>(x, bias, out);
}